// round 5
// baseline (speedup 1.0000x reference)
#include <cuda_runtime.h>

// ScoreMechain fused kernel — fp32, warp-per-TWO-samples, weights in shared.
// S=2: every per-lane weight load from shared is amortized over two samples,
// halving the dominant smem-crossbar traffic (ncu R3: L1=81.7% binding).

#define FULL 0xffffffffu

constexpr int J  = 17;
constexpr int NQ = 8;
constexpr int NWARP = 8;
constexpr int NT = NWARP * 32;

// shared-memory float offsets (weights identical to R3 layout)
constexpr int OFF_WUP4 = 0;            // [8][544][4] packed quads over input dim
constexpr int OFF_WUPT = 17408;        // [544][2]   tail inputs i=32,33
constexpr int OFF_BUP  = 18496;        // [544]
constexpr int OFF_PB   = 19040;        // [544] pbias
constexpr int OFF_WUD  = 19584;        // [32][32]
constexpr int OFF_WQ   = 20608;
constexpr int OFF_WK   = 21632;
constexpr int OFF_WV   = 22656;
constexpr int OFF_WD1  = 23680;
constexpr int OFF_WD2  = 24704;
constexpr int OFF_BQ   = 25728;
constexpr int OFF_BK   = 25760;
constexpr int OFF_BV   = 25792;
constexpr int OFF_BD1  = 25824;
constexpr int OFF_BD2  = 25856;
constexpr int OFF_WS   = 25888;
constexpr int OFF_BS   = 25920;        // 1 float (+3 pad)
constexpr int OFF_WARP = 25924;        // per-warp scratch base
// per-warp S=2 layout (floats):
//   bufU0[544] bufU1[544] bufA0[544] bufA1[544]
//   kpad0[564] kpad1[564] misc0[256] misc1[256]
constexpr int WSTRIDE  = 3816;
constexpr int SMEM_FLOATS = OFF_WARP + NWARP * WSTRIDE;   // 56452 -> 225808 B

__device__ int g_mask_mode;   // 0 = uint8 per element, 1 = 32-bit word per element

__device__ __forceinline__ float leaky(float v) { return v > 0.f ? v : 0.01f * v; }

// Detect mask dtype: reference guarantees exactly 9 nonzero entries per 17-row.
__global__ void detect_mask_kernel(const void* __restrict__ mraw)
{
    const unsigned char* m8 = (const unsigned char*)mraw;
    int lane = threadIdx.x;
    int bad8 = 0;
    #pragma unroll
    for (int s = 0; s < 2; s++) {
        int b = lane * 2 + s;
        int cnt = 0;
        for (int j = 0; j < J; j++) cnt += (m8[b * J + j] != 0);
        bad8 |= (cnt != 9);
    }
    unsigned any_bad = __ballot_sync(FULL, bad8);
    if (lane == 0) g_mask_mode = (any_bad == 0u) ? 0 : 1;
}

__global__ void __launch_bounds__(NT, 1)
score_mechain_kernel(const float* __restrict__ x,
                     const void* __restrict__ mraw,
                     const float* __restrict__ positions,
                     const float* __restrict__ W_up, const float* __restrict__ b_up,
                     const float* __restrict__ W_ud, const float* __restrict__ b_ud,
                     const float* __restrict__ W_q,  const float* __restrict__ b_q,
                     const float* __restrict__ W_k,  const float* __restrict__ b_k,
                     const float* __restrict__ W_v,  const float* __restrict__ b_v,
                     const float* __restrict__ W_d1, const float* __restrict__ b_d1,
                     const float* __restrict__ W_d2, const float* __restrict__ b_d2,
                     const float* __restrict__ W_s,  const float* __restrict__ b_s,
                     float* __restrict__ out, int B)
{
    extern __shared__ float smem[];
    const int tid = threadIdx.x;

    // ---------------- weight staging (once per CTA) ----------------
    for (int i = tid; i < 8 * 544 * 4; i += NT) {
        int iq = i / 2176, r = i % 2176, c = r >> 2, t = r & 3;
        smem[OFF_WUP4 + i] = W_up[(iq * 4 + t) * 544 + c];
    }
    for (int i = tid; i < 544 * 2; i += NT) {
        int c = i >> 1, t = i & 1;
        smem[OFF_WUPT + i] = W_up[(32 + t) * 544 + c];
    }
    for (int i = tid; i < 544; i += NT) smem[OFF_BUP + i] = b_up[i];
    for (int i = tid; i < 1024; i += NT) {
        smem[OFF_WUD + i] = W_ud[i];        // rows 0..31 of (64,32) row-major
        smem[OFF_WQ  + i] = W_q[i];
        smem[OFF_WK  + i] = W_k[i];
        smem[OFF_WV  + i] = W_v[i];
        smem[OFF_WD1 + i] = W_d1[i];
        smem[OFF_WD2 + i] = W_d2[i];
    }
    for (int i = tid; i < 32; i += NT) {
        smem[OFF_BQ  + i] = b_q[i];
        smem[OFF_BK  + i] = b_k[i];
        smem[OFF_BV  + i] = b_v[i];
        smem[OFF_BD1 + i] = b_d1[i];
        smem[OFF_BD2 + i] = b_d2[i];
        smem[OFF_WS  + i] = W_s[i];
    }
    if (tid == 0) smem[OFF_BS] = b_s[0];
    // pbias[j][o] = b_ud[o] + sum_h2 positions[j][h2] * W_ud[32+h2][o]
    for (int i = tid; i < 544; i += NT) {
        int j = i >> 5, o = i & 31;
        float acc = b_ud[o];
        #pragma unroll 8
        for (int h2 = 0; h2 < 32; h2++)
            acc += positions[j * 32 + h2] * W_ud[(32 + h2) * 32 + o];
        smem[OFF_PB + i] = acc;
    }
    __syncthreads();

    const int warpId = tid >> 5, lane = tid & 31;
    float* ws    = smem + OFF_WARP + warpId * WSTRIDE;
    float* bufU0 = ws;
    float* bufU1 = ws + 544;
    float* bufA0 = ws + 1088;
    float* bufA1 = ws + 1632;
    float* kpad0 = ws + 2176;   // k padded (17x33), later o-scratch (8x32)
    float* kpad1 = ws + 2740;
    float* misc0 = ws + 3304;   // x(34) -> q(8x32) -> p(8x20) -> d1-out(8x32)
    float* misc1 = ws + 3560;

    const int gw = blockIdx.x * NWARP + warpId;
    const int nw = gridDim.x * NWARP;
    const float iscale = 0.17677669529663687f;  // 1/sqrt(32)

    const int mask_mode = g_mask_mode;
    const unsigned char* mbase = (const unsigned char*)mraw;
    const int melt = (mask_mode == 0) ? 1 : 4;   // bytes per element

    for (int b0 = gw * 2; b0 < B; b0 += nw * 2) {
        const int b1 = b0 + 1;   // B even, b0 even -> always valid

        // ---- inputs ----
        misc0[lane] = x[b0 * 34 + lane];
        misc1[lane] = x[b1 * 34 + lane];
        if (lane < 2) {
            misc0[32 + lane] = x[b0 * 34 + 32 + lane];
            misc1[32 + lane] = x[b1 * 34 + 32 + lane];
        }
        unsigned mb0 = 1u, mb1 = 1u;
        if (lane < J) {
            const unsigned char* mp0 = mbase + ((size_t)b0 * J + lane) * melt;
            const unsigned char* mp1 = mbase + ((size_t)b1 * J + lane) * melt;
            unsigned v0 = mp0[0], v1 = mp1[0];
            if (melt == 4) { v0 |= mp0[1] | mp0[2] | mp0[3]; v1 |= mp1[1] | mp1[2] | mp1[3]; }
            mb0 = (v0 != 0u); mb1 = (v1 != 0u);
        }
        const unsigned occb0 = __ballot_sync(FULL, mb0 == 0u) & 0x1FFFFu;
        const unsigned occb1 = __ballot_sync(FULL, mb1 == 0u) & 0x1FFFFu;
        __syncwarp();

        // ---- up = leaky(x @ W_up + b_up) ----
        {
            float a0[J], a1[J];
            #pragma unroll
            for (int j = 0; j < J; j++) {
                float bv = smem[OFF_BUP + j * 32 + lane];
                a0[j] = bv; a1[j] = bv;
            }
            #pragma unroll
            for (int iq = 0; iq < 8; iq++) {
                float4 x0 = *reinterpret_cast<const float4*>(misc0 + 4 * iq);
                float4 x1 = *reinterpret_cast<const float4*>(misc1 + 4 * iq);
                #pragma unroll
                for (int j = 0; j < J; j++) {
                    float4 w = *reinterpret_cast<const float4*>(
                        smem + OFF_WUP4 + (iq * 544 + j * 32 + lane) * 4);
                    a0[j] += x0.x * w.x + x0.y * w.y + x0.z * w.z + x0.w * w.w;
                    a1[j] += x1.x * w.x + x1.y * w.y + x1.z * w.z + x1.w * w.w;
                }
            }
            {
                float xa0 = misc0[32], xb0 = misc0[33];
                float xa1 = misc1[32], xb1 = misc1[33];
                #pragma unroll
                for (int j = 0; j < J; j++) {
                    float2 w = *reinterpret_cast<const float2*>(
                        smem + OFF_WUPT + (j * 32 + lane) * 2);
                    a0[j] += xa0 * w.x + xb0 * w.y;
                    a1[j] += xa1 * w.x + xb1 * w.y;
                }
            }
            #pragma unroll
            for (int j = 0; j < J; j++) {
                bufU0[j * 32 + lane] = leaky(a0[j]);
                bufU1[j * 32 + lane] = leaky(a1[j]);
            }
        }
        __syncwarp();

        // ---- u = leaky(up @ Wud_top + pbias) ----
        {
            float a0[J], a1[J];
            #pragma unroll
            for (int j = 0; j < J; j++) {
                float pv = smem[OFF_PB + j * 32 + lane];
                a0[j] = pv; a1[j] = pv;
            }
            #pragma unroll
            for (int hq = 0; hq < 8; hq++) {
                float w0 = smem[OFF_WUD + (4 * hq + 0) * 32 + lane];
                float w1 = smem[OFF_WUD + (4 * hq + 1) * 32 + lane];
                float w2 = smem[OFF_WUD + (4 * hq + 2) * 32 + lane];
                float w3 = smem[OFF_WUD + (4 * hq + 3) * 32 + lane];
                #pragma unroll
                for (int j = 0; j < J; j++) {
                    float4 u0 = *reinterpret_cast<const float4*>(bufU0 + j * 32 + 4 * hq);
                    float4 u1 = *reinterpret_cast<const float4*>(bufU1 + j * 32 + 4 * hq);
                    a0[j] += u0.x * w0 + u0.y * w1 + u0.z * w2 + u0.w * w3;
                    a1[j] += u1.x * w0 + u1.y * w1 + u1.z * w2 + u1.w * w3;
                }
            }
            #pragma unroll
            for (int j = 0; j < J; j++) {
                bufA0[j * 32 + lane] = leaky(a0[j]);
                bufA1[j * 32 + lane] = leaky(a1[j]);
            }
        }
        __syncwarp();

        // ---- k (all joints) ----
        {
            float a0[J], a1[J];
            #pragma unroll
            for (int j = 0; j < J; j++) {
                float bv = smem[OFF_BK + lane];
                a0[j] = bv; a1[j] = bv;
            }
            #pragma unroll
            for (int hq = 0; hq < 8; hq++) {
                float w0 = smem[OFF_WK + (4 * hq + 0) * 32 + lane];
                float w1 = smem[OFF_WK + (4 * hq + 1) * 32 + lane];
                float w2 = smem[OFF_WK + (4 * hq + 2) * 32 + lane];
                float w3 = smem[OFF_WK + (4 * hq + 3) * 32 + lane];
                #pragma unroll
                for (int j = 0; j < J; j++) {
                    float4 u0 = *reinterpret_cast<const float4*>(bufA0 + j * 32 + 4 * hq);
                    float4 u1 = *reinterpret_cast<const float4*>(bufA1 + j * 32 + 4 * hq);
                    a0[j] += u0.x * w0 + u0.y * w1 + u0.z * w2 + u0.w * w3;
                    a1[j] += u1.x * w0 + u1.y * w1 + u1.z * w2 + u1.w * w3;
                }
            }
            #pragma unroll
            for (int j = 0; j < J; j++) {
                kpad0[j * 33 + lane] = a0[j];
                kpad1[j * 33 + lane] = a1[j];
            }
        }

        // ---- q (occluded joints only) ----
        {
            int oj0[NQ], oj1[NQ];
            unsigned t0 = occb0, t1 = occb1;
            #pragma unroll
            for (int t = 0; t < NQ; t++) {
                oj0[t] = __ffs(t0) - 1; t0 &= t0 - 1;
                oj1[t] = __ffs(t1) - 1; t1 &= t1 - 1;
            }
            float a0[NQ], a1[NQ];
            #pragma unroll
            for (int t = 0; t < NQ; t++) {
                float bv = smem[OFF_BQ + lane];
                a0[t] = bv; a1[t] = bv;
            }
            #pragma unroll
            for (int hq = 0; hq < 8; hq++) {
                float w0 = smem[OFF_WQ + (4 * hq + 0) * 32 + lane];
                float w1 = smem[OFF_WQ + (4 * hq + 1) * 32 + lane];
                float w2 = smem[OFF_WQ + (4 * hq + 2) * 32 + lane];
                float w3 = smem[OFF_WQ + (4 * hq + 3) * 32 + lane];
                #pragma unroll
                for (int t = 0; t < NQ; t++) {
                    float4 u0 = *reinterpret_cast<const float4*>(bufA0 + oj0[t] * 32 + 4 * hq);
                    float4 u1 = *reinterpret_cast<const float4*>(bufA1 + oj1[t] * 32 + 4 * hq);
                    a0[t] += u0.x * w0 + u0.y * w1 + u0.z * w2 + u0.w * w3;
                    a1[t] += u1.x * w0 + u1.y * w1 + u1.z * w2 + u1.w * w3;
                }
            }
            __syncwarp();   // x dead; misc becomes q
            #pragma unroll
            for (int t = 0; t < NQ; t++) {
                misc0[t * 32 + lane] = a0[t];
                misc1[t * 32 + lane] = a1[t];
            }
        }

        // ---- v (all joints) — overwrites bufA after all u reads done ----
        {
            float a0[J], a1[J];
            #pragma unroll
            for (int j = 0; j < J; j++) {
                float bv = smem[OFF_BV + lane];
                a0[j] = bv; a1[j] = bv;
            }
            #pragma unroll
            for (int hq = 0; hq < 8; hq++) {
                float w0 = smem[OFF_WV + (4 * hq + 0) * 32 + lane];
                float w1 = smem[OFF_WV + (4 * hq + 1) * 32 + lane];
                float w2 = smem[OFF_WV + (4 * hq + 2) * 32 + lane];
                float w3 = smem[OFF_WV + (4 * hq + 3) * 32 + lane];
                #pragma unroll
                for (int j = 0; j < J; j++) {
                    float4 u0 = *reinterpret_cast<const float4*>(bufA0 + j * 32 + 4 * hq);
                    float4 u1 = *reinterpret_cast<const float4*>(bufA1 + j * 32 + 4 * hq);
                    a0[j] += u0.x * w0 + u0.y * w1 + u0.z * w2 + u0.w * w3;
                    a1[j] += u1.x * w0 + u1.y * w1 + u1.z * w2 + u1.w * w3;
                }
            }
            __syncwarp();   // all u reads done before overwrite
            #pragma unroll
            for (int j = 0; j < J; j++) {
                bufA0[j * 32 + lane] = a0[j];
                bufA1[j * 32 + lane] = a1[j];
            }
        }
        __syncwarp();

        // ---- scores: lane = key joint ----
        {
            float s0[NQ], s1[NQ];
            #pragma unroll
            for (int t = 0; t < NQ; t++) { s0[t] = 0.f; s1[t] = 0.f; }
            #pragma unroll 8
            for (int h = 0; h < 32; h++) {
                float k0 = (lane < J) ? kpad0[lane * 33 + h] : 0.f;
                float k1 = (lane < J) ? kpad1[lane * 33 + h] : 0.f;
                #pragma unroll
                for (int t = 0; t < NQ; t++) {
                    s0[t] += misc0[t * 32 + h] * k0;
                    s1[t] += misc1[t * 32 + h] * k1;
                }
            }
            __syncwarp();   // q fully consumed; misc becomes p
            #pragma unroll
            for (int t = 0; t < NQ; t++) {
                float sa = (lane < J) ? s0[t] * iscale : -1e30f;
                float mx = sa;
                #pragma unroll
                for (int o = 16; o > 0; o >>= 1)
                    mx = fmaxf(mx, __shfl_xor_sync(FULL, mx, o));
                float e = (lane < J) ? __expf(sa - mx) : 0.f;
                float sum = e;
                #pragma unroll
                for (int o = 16; o > 0; o >>= 1)
                    sum += __shfl_xor_sync(FULL, sum, o);
                if (lane < J) misc0[t * 20 + lane] = __fdividef(e, sum);

                float sb = (lane < J) ? s1[t] * iscale : -1e30f;
                float my = sb;
                #pragma unroll
                for (int o = 16; o > 0; o >>= 1)
                    my = fmaxf(my, __shfl_xor_sync(FULL, my, o));
                float e1 = (lane < J) ? __expf(sb - my) : 0.f;
                float sum1 = e1;
                #pragma unroll
                for (int o = 16; o > 0; o >>= 1)
                    sum1 += __shfl_xor_sync(FULL, sum1, o);
                if (lane < J) misc1[t * 20 + lane] = __fdividef(e1, sum1);
            }
        }
        __syncwarp();

        // ---- o = att @ v : lane = h ----
        {
            float o0[NQ], o1[NQ];
            #pragma unroll
            for (int t = 0; t < NQ; t++) { o0[t] = 0.f; o1[t] = 0.f; }
            #pragma unroll
            for (int j = 0; j < J; j++) {
                float v0 = bufA0[j * 32 + lane];
                float v1 = bufA1[j * 32 + lane];
                #pragma unroll
                for (int t = 0; t < NQ; t++) {
                    o0[t] += misc0[t * 20 + j] * v0;
                    o1[t] += misc1[t * 20 + j] * v1;
                }
            }
            __syncwarp();   // k dead; kpad becomes o-scratch
            #pragma unroll
            for (int t = 0; t < NQ; t++) {
                kpad0[t * 32 + lane] = o0[t];
                kpad1[t * 32 + lane] = o1[t];
            }
        }
        __syncwarp();

        // ---- d1 ----
        {
            float a0[NQ], a1[NQ];
            #pragma unroll
            for (int t = 0; t < NQ; t++) {
                float bv = smem[OFF_BD1 + lane];
                a0[t] = bv; a1[t] = bv;
            }
            #pragma unroll
            for (int hq = 0; hq < 8; hq++) {
                float w0 = smem[OFF_WD1 + (4 * hq + 0) * 32 + lane];
                float w1 = smem[OFF_WD1 + (4 * hq + 1) * 32 + lane];
                float w2 = smem[OFF_WD1 + (4 * hq + 2) * 32 + lane];
                float w3 = smem[OFF_WD1 + (4 * hq + 3) * 32 + lane];
                #pragma unroll
                for (int t = 0; t < NQ; t++) {
                    float4 u0 = *reinterpret_cast<const float4*>(kpad0 + t * 32 + 4 * hq);
                    float4 u1 = *reinterpret_cast<const float4*>(kpad1 + t * 32 + 4 * hq);
                    a0[t] += u0.x * w0 + u0.y * w1 + u0.z * w2 + u0.w * w3;
                    a1[t] += u1.x * w0 + u1.y * w1 + u1.z * w2 + u1.w * w3;
                }
            }
            __syncwarp();   // p dead; misc becomes d1 output
            #pragma unroll
            for (int t = 0; t < NQ; t++) {
                misc0[t * 32 + lane] = leaky(a0[t]);
                misc1[t * 32 + lane] = leaky(a1[t]);
            }
        }
        __syncwarp();

        // ---- d2 + residual, then final reduce + sigmoid ----
        {
            int oj0[NQ], oj1[NQ];
            unsigned t0 = occb0, t1 = occb1;
            #pragma unroll
            for (int t = 0; t < NQ; t++) {
                oj0[t] = __ffs(t0) - 1; t0 &= t0 - 1;
                oj1[t] = __ffs(t1) - 1; t1 &= t1 - 1;
            }
            float a0[NQ], a1[NQ];
            #pragma unroll
            for (int t = 0; t < NQ; t++) {
                float bv = smem[OFF_BD2 + lane];
                a0[t] = bv + bufU0[oj0[t] * 32 + lane];
                a1[t] = bv + bufU1[oj1[t] * 32 + lane];
            }
            #pragma unroll
            for (int hq = 0; hq < 8; hq++) {
                float w0 = smem[OFF_WD2 + (4 * hq + 0) * 32 + lane];
                float w1 = smem[OFF_WD2 + (4 * hq + 1) * 32 + lane];
                float w2 = smem[OFF_WD2 + (4 * hq + 2) * 32 + lane];
                float w3 = smem[OFF_WD2 + (4 * hq + 3) * 32 + lane];
                #pragma unroll
                for (int t = 0; t < NQ; t++) {
                    float4 u0 = *reinterpret_cast<const float4*>(misc0 + t * 32 + 4 * hq);
                    float4 u1 = *reinterpret_cast<const float4*>(misc1 + t * 32 + 4 * hq);
                    a0[t] += u0.x * w0 + u0.y * w1 + u0.z * w2 + u0.w * w3;
                    a1[t] += u1.x * w0 + u1.y * w1 + u1.z * w2 + u1.w * w3;
                }
            }

            float wsv = smem[OFF_WS + lane];
            float out0 = 0.f, out1 = 0.f;
            #pragma unroll
            for (int t = 0; t < NQ; t++) {
                float v0 = a0[t] * wsv;
                float v1 = a1[t] * wsv;
                #pragma unroll
                for (int o = 16; o > 0; o >>= 1) {
                    v0 += __shfl_xor_sync(FULL, v0, o);
                    v1 += __shfl_xor_sync(FULL, v1, o);
                }
                if (lane == t) { out0 = v0; out1 = v1; }
            }
            if (lane < NQ) {
                float bs = smem[OFF_BS];
                out[b0 * NQ + lane] = __fdividef(1.f, 1.f + __expf(-(out0 + bs)));
                out[b1 * NQ + lane] = __fdividef(1.f, 1.f + __expf(-(out1 + bs)));
            }
        }
        __syncwarp();   // scratch reused next iteration
    }
}

extern "C" void kernel_launch(void* const* d_in, const int* in_sizes, int n_in,
                              void* d_out, int out_size)
{
    const float* x         = (const float*)d_in[0];
    const void*  mraw      = d_in[1];
    const float* positions = (const float*)d_in[2];
    const float* W_up = (const float*)d_in[3];
    const float* b_up = (const float*)d_in[4];
    const float* W_ud = (const float*)d_in[5];
    const float* b_ud = (const float*)d_in[6];
    const float* W_q  = (const float*)d_in[7];
    const float* b_q  = (const float*)d_in[8];
    const float* W_k  = (const float*)d_in[9];
    const float* b_k  = (const float*)d_in[10];
    const float* W_v  = (const float*)d_in[11];
    const float* b_v  = (const float*)d_in[12];
    const float* W_d1 = (const float*)d_in[13];
    const float* b_d1 = (const float*)d_in[14];
    const float* W_d2 = (const float*)d_in[15];
    const float* b_d2 = (const float*)d_in[16];
    const float* W_s  = (const float*)d_in[17];
    const float* b_s  = (const float*)d_in[18];
    float* out = (float*)d_out;

    const int B = in_sizes[0] / 34;
    const size_t smem_bytes = (size_t)SMEM_FLOATS * sizeof(float);

    detect_mask_kernel<<<1, 32>>>(mraw);

    cudaFuncSetAttribute(score_mechain_kernel,
                         cudaFuncAttributeMaxDynamicSharedMemorySize,
                         (int)smem_bytes);
    score_mechain_kernel<<<148, NT, smem_bytes>>>(
        x, mraw, positions, W_up, b_up, W_ud, b_ud, W_q, b_q, W_k, b_k,
        W_v, b_v, W_d1, b_d1, W_d2, b_d2, W_s, b_s, out, B);
}

// round 6
// speedup vs baseline: 1.7087x; 1.7087x over previous
#include <cuda_runtime.h>

// ScoreMechain fused kernel — fp32, warp-per-TWO-samples, NWARP=12,
// sample-interleaved activations in shared + fma.rn.f32x2 packed math.

#define FULL 0xffffffffu
typedef unsigned long long u64;

constexpr int J  = 17;
constexpr int NQ = 8;
constexpr int NWARP = 12;
constexpr int NT = NWARP * 32;

// shared-memory float offsets
constexpr int OFF_WUP4 = 0;            // [8][544][4] quad-packed over input dim
constexpr int OFF_WUPT = 17408;        // [544][2] tail inputs i=32,33
constexpr int OFF_PB   = 18496;        // [544] pbias
constexpr int OFF_WUD  = 19040;        // [32][32]
constexpr int OFF_WQ   = 20064;
constexpr int OFF_WK   = 21088;
constexpr int OFF_WV   = 22112;
constexpr int OFF_WD1  = 23136;
constexpr int OFF_WD2  = 24160;
constexpr int OFF_BQ   = 25184;
constexpr int OFF_BK   = 25216;
constexpr int OFF_BV   = 25248;
constexpr int OFF_BD1  = 25280;
constexpr int OFF_BD2  = 25312;
constexpr int OFF_WS   = 25344;
constexpr int OFF_BS   = 25376;        // 1 float (+3 pad)
constexpr int OFF_WARP = 25380;        // per-warp scratch base (16B aligned)
// per-warp scratch (floats), all sample-interleaved (s0,s1) pairs:
//   bufA[17][64]  up -> u -> v
//   kpad[17][66]  k (stride 66 for conflict-free transposed reads); later o[8][64]
//   misc[512]     x-pairs(68) -> q[8][64] -> p[8][40] -> d1out[8][64]
constexpr int WSTRIDE = 2724;          // 1088 + 1124 + 512, 16B aligned
constexpr int SMEM_FLOATS = OFF_WARP + NWARP * WSTRIDE;   // 58068 -> 232272 B

__device__ int g_mask_mode;   // 0 = uint8 per element, 1 = 32-bit word per element

__device__ __forceinline__ float leaky(float v) { return v > 0.f ? v : 0.01f * v; }

__device__ __forceinline__ u64 pack2(float lo, float hi) {
    u64 r; asm("mov.b64 %0,{%1,%2};" : "=l"(r) : "f"(lo), "f"(hi)); return r;
}
__device__ __forceinline__ void unpack2(u64 v, float& lo, float& hi) {
    asm("mov.b64 {%0,%1},%2;" : "=f"(lo), "=f"(hi) : "l"(v));
}
__device__ __forceinline__ u64 ffma2(u64 a, u64 b, u64 c) {
    u64 d; asm("fma.rn.f32x2 %0,%1,%2,%3;" : "=l"(d) : "l"(a), "l"(b), "l"(c)); return d;
}
__device__ __forceinline__ u64 fmul2(u64 a, u64 b) {
    u64 d; asm("mul.rn.f32x2 %0,%1,%2;" : "=l"(d) : "l"(a), "l"(b)); return d;
}
__device__ __forceinline__ u64 fadd2(u64 a, u64 b) {
    u64 d; asm("add.rn.f32x2 %0,%1,%2;" : "=l"(d) : "l"(a), "l"(b)); return d;
}
__device__ __forceinline__ u64 leaky2(u64 v) {
    float a, b; unpack2(v, a, b); return pack2(leaky(a), leaky(b));
}

// Detect mask dtype: reference guarantees exactly 9 nonzero entries per 17-row.
__global__ void detect_mask_kernel(const void* __restrict__ mraw)
{
    const unsigned char* m8 = (const unsigned char*)mraw;
    int lane = threadIdx.x;
    int bad8 = 0;
    #pragma unroll
    for (int s = 0; s < 2; s++) {
        int b = lane * 2 + s;
        int cnt = 0;
        for (int j = 0; j < J; j++) cnt += (m8[b * J + j] != 0);
        bad8 |= (cnt != 9);
    }
    unsigned any_bad = __ballot_sync(FULL, bad8);
    if (lane == 0) g_mask_mode = (any_bad == 0u) ? 0 : 1;
}

__global__ void __launch_bounds__(NT, 1)
score_mechain_kernel(const float* __restrict__ x,
                     const void* __restrict__ mraw,
                     const float* __restrict__ positions,
                     const float* __restrict__ W_up, const float* __restrict__ b_up,
                     const float* __restrict__ W_ud, const float* __restrict__ b_ud,
                     const float* __restrict__ W_q,  const float* __restrict__ b_q,
                     const float* __restrict__ W_k,  const float* __restrict__ b_k,
                     const float* __restrict__ W_v,  const float* __restrict__ b_v,
                     const float* __restrict__ W_d1, const float* __restrict__ b_d1,
                     const float* __restrict__ W_d2, const float* __restrict__ b_d2,
                     const float* __restrict__ W_s,  const float* __restrict__ b_s,
                     float* __restrict__ out, int B)
{
    extern __shared__ float smem[];
    const int tid = threadIdx.x;

    // ---------------- weight staging (once per CTA) ----------------
    for (int i = tid; i < 8 * 544 * 4; i += NT) {
        int iq = i / 2176, r = i % 2176, c = r >> 2, t = r & 3;
        smem[OFF_WUP4 + i] = W_up[(iq * 4 + t) * 544 + c];
    }
    for (int i = tid; i < 544 * 2; i += NT) {
        int c = i >> 1, t = i & 1;
        smem[OFF_WUPT + i] = W_up[(32 + t) * 544 + c];
    }
    for (int i = tid; i < 1024; i += NT) {
        smem[OFF_WUD + i] = W_ud[i];        // rows 0..31 of (64,32) row-major
        smem[OFF_WQ  + i] = W_q[i];
        smem[OFF_WK  + i] = W_k[i];
        smem[OFF_WV  + i] = W_v[i];
        smem[OFF_WD1 + i] = W_d1[i];
        smem[OFF_WD2 + i] = W_d2[i];
    }
    for (int i = tid; i < 32; i += NT) {
        smem[OFF_BQ  + i] = b_q[i];
        smem[OFF_BK  + i] = b_k[i];
        smem[OFF_BV  + i] = b_v[i];
        smem[OFF_BD1 + i] = b_d1[i];
        smem[OFF_BD2 + i] = b_d2[i];
        smem[OFF_WS  + i] = W_s[i];
    }
    if (tid == 0) smem[OFF_BS] = b_s[0];
    // pbias[j][o] = b_ud[o] + sum_h2 positions[j][h2] * W_ud[32+h2][o]
    for (int i = tid; i < 544; i += NT) {
        int j = i >> 5, o = i & 31;
        float acc = b_ud[o];
        #pragma unroll 8
        for (int h2 = 0; h2 < 32; h2++)
            acc += positions[j * 32 + h2] * W_ud[(32 + h2) * 32 + o];
        smem[OFF_PB + i] = acc;
    }
    __syncthreads();

    const int warpId = tid >> 5, lane = tid & 31;
    float* ws   = smem + OFF_WARP + warpId * WSTRIDE;
    float* bufA = ws;              // up -> u -> v   (17 rows x 64)
    float* kpad = ws + 1088;       // k (17 x 66) -> o (8 x 64)
    float* misc = ws + 2212;       // x-pairs -> q (8x64) -> p (8x40) -> d1out (8x64)

    const int gw = blockIdx.x * NWARP + warpId;
    const int nw = gridDim.x * NWARP;
    const float iscale = 0.17677669529663687f;  // 1/sqrt(32)

    const int mask_mode = g_mask_mode;
    const unsigned char* mbase = (const unsigned char*)mraw;
    const int melt = (mask_mode == 0) ? 1 : 4;   // bytes per element

    for (int b0 = gw * 2; b0 < B; b0 += nw * 2) {
        const int b1 = b0 + 1;   // B even -> always valid

        // ---- inputs: x packed (s0,s1) pairs ----
        {
            float x0v = x[b0 * 34 + lane];
            float x1v = x[b1 * 34 + lane];
            *(u64*)(misc + 2 * lane) = pack2(x0v, x1v);
            if (lane < 2) {
                float t0 = x[b0 * 34 + 32 + lane];
                float t1 = x[b1 * 34 + 32 + lane];
                *(u64*)(misc + 64 + 2 * lane) = pack2(t0, t1);
            }
        }
        unsigned mb0 = 1u, mb1 = 1u;
        if (lane < J) {
            const unsigned char* mp0 = mbase + ((size_t)b0 * J + lane) * melt;
            const unsigned char* mp1 = mbase + ((size_t)b1 * J + lane) * melt;
            unsigned v0 = mp0[0], v1 = mp1[0];
            if (melt == 4) { v0 |= mp0[1] | mp0[2] | mp0[3]; v1 |= mp1[1] | mp1[2] | mp1[3]; }
            mb0 = (v0 != 0u); mb1 = (v1 != 0u);
        }
        const unsigned occb0 = __ballot_sync(FULL, mb0 == 0u) & 0x1FFFFu;
        const unsigned occb1 = __ballot_sync(FULL, mb1 == 0u) & 0x1FFFFu;
        int oj0[NQ], oj1[NQ];
        {
            unsigned t0 = occb0, t1 = occb1;
            #pragma unroll
            for (int t = 0; t < NQ; t++) {
                oj0[t] = __ffs(t0) - 1; t0 &= t0 - 1;
                oj1[t] = __ffs(t1) - 1; t1 &= t1 - 1;
            }
        }
        __syncwarp();

        // ---- up = leaky(x @ W_up + b_up); residual columns -> registers ----
        float r0[NQ], r1[NQ];
        {
            float a0[J], a1[J];
            #pragma unroll
            for (int j = 0; j < J; j++) {
                float bv = __ldg(&b_up[j * 32 + lane]);
                a0[j] = bv; a1[j] = bv;
            }
            #pragma unroll
            for (int iq = 0; iq < 8; iq++) {
                float4 xa = *reinterpret_cast<const float4*>(misc + 8 * iq);
                float4 xb = *reinterpret_cast<const float4*>(misc + 8 * iq + 4);
                // xa = (x0[4iq], x1[4iq], x0[4iq+1], x1[4iq+1]); xb likewise +2
                #pragma unroll
                for (int j = 0; j < J; j++) {
                    float4 w = *reinterpret_cast<const float4*>(
                        smem + OFF_WUP4 + (iq * 544 + j * 32 + lane) * 4);
                    a0[j] += xa.x * w.x + xa.z * w.y + xb.x * w.z + xb.z * w.w;
                    a1[j] += xa.y * w.x + xa.w * w.y + xb.y * w.z + xb.w * w.w;
                }
            }
            {
                u64 p32 = *(const u64*)(misc + 64);
                u64 p33 = *(const u64*)(misc + 66);
                float x32a, x32b, x33a, x33b;
                unpack2(p32, x32a, x32b); unpack2(p33, x33a, x33b);
                #pragma unroll
                for (int j = 0; j < J; j++) {
                    float2 w = *reinterpret_cast<const float2*>(
                        smem + OFF_WUPT + (j * 32 + lane) * 2);
                    a0[j] += x32a * w.x + x33a * w.y;
                    a1[j] += x32b * w.x + x33b * w.y;
                }
            }
            #pragma unroll
            for (int t = 0; t < NQ; t++) { r0[t] = 0.f; r1[t] = 0.f; }
            __syncwarp();   // x-pair reads complete everywhere before overwrite risk
            #pragma unroll
            for (int j = 0; j < J; j++) {
                float l0 = leaky(a0[j]), l1 = leaky(a1[j]);
                *(u64*)(bufA + j * 64 + 2 * lane) = pack2(l0, l1);
                #pragma unroll
                for (int t = 0; t < NQ; t++) {
                    if (j == oj0[t]) r0[t] = l0;
                    if (j == oj1[t]) r1[t] = l1;
                }
            }
        }
        __syncwarp();

        // ---- u = leaky(up @ Wud_top + pbias), packed (overwrites up in place) ----
        {
            u64 acc[J];
            #pragma unroll
            for (int j = 0; j < J; j++) {
                float pv = smem[OFF_PB + j * 32 + lane];
                acc[j] = pack2(pv, pv);
            }
            #pragma unroll
            for (int hq = 0; hq < 8; hq++) {
                u64 w0 = pack2(smem[OFF_WUD + (4 * hq + 0) * 32 + lane], smem[OFF_WUD + (4 * hq + 0) * 32 + lane]);
                u64 w1 = pack2(smem[OFF_WUD + (4 * hq + 1) * 32 + lane], smem[OFF_WUD + (4 * hq + 1) * 32 + lane]);
                u64 w2 = pack2(smem[OFF_WUD + (4 * hq + 2) * 32 + lane], smem[OFF_WUD + (4 * hq + 2) * 32 + lane]);
                u64 w3 = pack2(smem[OFF_WUD + (4 * hq + 3) * 32 + lane], smem[OFF_WUD + (4 * hq + 3) * 32 + lane]);
                #pragma unroll
                for (int j = 0; j < J; j++) {
                    ulonglong2 qa = *reinterpret_cast<const ulonglong2*>(bufA + j * 64 + 8 * hq);
                    ulonglong2 qb = *reinterpret_cast<const ulonglong2*>(bufA + j * 64 + 8 * hq + 4);
                    acc[j] = ffma2(qa.x, w0, acc[j]);
                    acc[j] = ffma2(qa.y, w1, acc[j]);
                    acc[j] = ffma2(qb.x, w2, acc[j]);
                    acc[j] = ffma2(qb.y, w3, acc[j]);
                }
            }
            __syncwarp();   // all up reads done before overwrite
            #pragma unroll
            for (int j = 0; j < J; j++)
                *(u64*)(bufA + j * 64 + 2 * lane) = leaky2(acc[j]);
        }
        __syncwarp();

        // ---- k = u @ Wk + bk (packed) -> kpad transposed-readable ----
        {
            u64 acc[J];
            float bk = smem[OFF_BK + lane];
            u64 bk2 = pack2(bk, bk);
            #pragma unroll
            for (int j = 0; j < J; j++) acc[j] = bk2;
            #pragma unroll
            for (int hq = 0; hq < 8; hq++) {
                u64 w0 = pack2(smem[OFF_WK + (4 * hq + 0) * 32 + lane], smem[OFF_WK + (4 * hq + 0) * 32 + lane]);
                u64 w1 = pack2(smem[OFF_WK + (4 * hq + 1) * 32 + lane], smem[OFF_WK + (4 * hq + 1) * 32 + lane]);
                u64 w2 = pack2(smem[OFF_WK + (4 * hq + 2) * 32 + lane], smem[OFF_WK + (4 * hq + 2) * 32 + lane]);
                u64 w3 = pack2(smem[OFF_WK + (4 * hq + 3) * 32 + lane], smem[OFF_WK + (4 * hq + 3) * 32 + lane]);
                #pragma unroll
                for (int j = 0; j < J; j++) {
                    ulonglong2 qa = *reinterpret_cast<const ulonglong2*>(bufA + j * 64 + 8 * hq);
                    ulonglong2 qb = *reinterpret_cast<const ulonglong2*>(bufA + j * 64 + 8 * hq + 4);
                    acc[j] = ffma2(qa.x, w0, acc[j]);
                    acc[j] = ffma2(qa.y, w1, acc[j]);
                    acc[j] = ffma2(qb.x, w2, acc[j]);
                    acc[j] = ffma2(qb.y, w3, acc[j]);
                }
            }
            #pragma unroll
            for (int j = 0; j < J; j++)
                *(u64*)(kpad + j * 66 + 2 * lane) = acc[j];
        }

        // ---- q (occluded rows; scalar GEMM, packed store) ----
        {
            float a0[NQ], a1[NQ];
            float bq = smem[OFF_BQ + lane];
            #pragma unroll
            for (int t = 0; t < NQ; t++) { a0[t] = bq; a1[t] = bq; }
            #pragma unroll
            for (int hq = 0; hq < 8; hq++) {
                float w0 = smem[OFF_WQ + (4 * hq + 0) * 32 + lane];
                float w1 = smem[OFF_WQ + (4 * hq + 1) * 32 + lane];
                float w2 = smem[OFF_WQ + (4 * hq + 2) * 32 + lane];
                float w3 = smem[OFF_WQ + (4 * hq + 3) * 32 + lane];
                #pragma unroll
                for (int t = 0; t < NQ; t++) {
                    float4 ua = *reinterpret_cast<const float4*>(bufA + oj0[t] * 64 + 8 * hq);
                    float4 ub = *reinterpret_cast<const float4*>(bufA + oj0[t] * 64 + 8 * hq + 4);
                    a0[t] += ua.x * w0 + ua.z * w1 + ub.x * w2 + ub.z * w3;
                    float4 va = *reinterpret_cast<const float4*>(bufA + oj1[t] * 64 + 8 * hq);
                    float4 vb = *reinterpret_cast<const float4*>(bufA + oj1[t] * 64 + 8 * hq + 4);
                    a1[t] += va.y * w0 + va.w * w1 + vb.y * w2 + vb.w * w3;
                }
            }
            __syncwarp();   // x-pairs dead; misc becomes q
            #pragma unroll
            for (int t = 0; t < NQ; t++)
                *(u64*)(misc + t * 64 + 2 * lane) = pack2(a0[t], a1[t]);
        }

        // ---- v = u @ Wv + bv (packed; overwrites u after all reads) ----
        {
            u64 acc[J];
            float bv = smem[OFF_BV + lane];
            u64 bv2 = pack2(bv, bv);
            #pragma unroll
            for (int j = 0; j < J; j++) acc[j] = bv2;
            #pragma unroll
            for (int hq = 0; hq < 8; hq++) {
                u64 w0 = pack2(smem[OFF_WV + (4 * hq + 0) * 32 + lane], smem[OFF_WV + (4 * hq + 0) * 32 + lane]);
                u64 w1 = pack2(smem[OFF_WV + (4 * hq + 1) * 32 + lane], smem[OFF_WV + (4 * hq + 1) * 32 + lane]);
                u64 w2 = pack2(smem[OFF_WV + (4 * hq + 2) * 32 + lane], smem[OFF_WV + (4 * hq + 2) * 32 + lane]);
                u64 w3 = pack2(smem[OFF_WV + (4 * hq + 3) * 32 + lane], smem[OFF_WV + (4 * hq + 3) * 32 + lane]);
                #pragma unroll
                for (int j = 0; j < J; j++) {
                    ulonglong2 qa = *reinterpret_cast<const ulonglong2*>(bufA + j * 64 + 8 * hq);
                    ulonglong2 qb = *reinterpret_cast<const ulonglong2*>(bufA + j * 64 + 8 * hq + 4);
                    acc[j] = ffma2(qa.x, w0, acc[j]);
                    acc[j] = ffma2(qa.y, w1, acc[j]);
                    acc[j] = ffma2(qb.x, w2, acc[j]);
                    acc[j] = ffma2(qb.y, w3, acc[j]);
                }
            }
            __syncwarp();   // all u reads done
            #pragma unroll
            for (int j = 0; j < J; j++)
                *(u64*)(bufA + j * 64 + 2 * lane) = acc[j];
        }
        __syncwarp();

        // ---- scores (packed): lane = key joint ----
        {
            const float* krow = kpad + (lane < J ? lane : 0) * 66;
            u64 s[NQ];
            #pragma unroll
            for (int t = 0; t < NQ; t++) s[t] = 0ull;
            #pragma unroll
            for (int h = 0; h < 32; h++) {
                u64 kp = *(const u64*)(krow + 2 * h);
                #pragma unroll
                for (int t = 0; t < NQ; t++) {
                    u64 qp = *(const u64*)(misc + t * 64 + 2 * h);
                    s[t] = ffma2(kp, qp, s[t]);
                }
            }
            __syncwarp();   // q fully consumed; misc becomes p
            #pragma unroll
            for (int t = 0; t < NQ; t++) {
                float sa, sb; unpack2(s[t], sa, sb);
                float s0 = (lane < J) ? sa * iscale : -1e30f;
                float mx = s0;
                #pragma unroll
                for (int o = 16; o > 0; o >>= 1)
                    mx = fmaxf(mx, __shfl_xor_sync(FULL, mx, o));
                float e0 = (lane < J) ? __expf(s0 - mx) : 0.f;
                float sum0 = e0;
                #pragma unroll
                for (int o = 16; o > 0; o >>= 1)
                    sum0 += __shfl_xor_sync(FULL, sum0, o);
                float p0 = __fdividef(e0, sum0);

                float s1 = (lane < J) ? sb * iscale : -1e30f;
                float my = s1;
                #pragma unroll
                for (int o = 16; o > 0; o >>= 1)
                    my = fmaxf(my, __shfl_xor_sync(FULL, my, o));
                float e1 = (lane < J) ? __expf(s1 - my) : 0.f;
                float sum1 = e1;
                #pragma unroll
                for (int o = 16; o > 0; o >>= 1)
                    sum1 += __shfl_xor_sync(FULL, sum1, o);
                float p1 = __fdividef(e1, sum1);

                if (lane < J)
                    *(u64*)(misc + t * 40 + 2 * lane) = pack2(p0, p1);
            }
        }
        __syncwarp();

        // ---- o = att @ v (packed): lane = h ----
        {
            u64 o8[NQ];
            #pragma unroll
            for (int t = 0; t < NQ; t++) o8[t] = 0ull;
            #pragma unroll
            for (int j = 0; j < J; j++) {
                u64 vp = *(const u64*)(bufA + j * 64 + 2 * lane);
                #pragma unroll
                for (int t = 0; t < NQ; t++) {
                    u64 pp = *(const u64*)(misc + t * 40 + 2 * j);
                    o8[t] = ffma2(vp, pp, o8[t]);
                }
            }
            __syncwarp();   // k dead; kpad becomes o-scratch (stride 64)
            #pragma unroll
            for (int t = 0; t < NQ; t++)
                *(u64*)(kpad + t * 64 + 2 * lane) = o8[t];
        }
        __syncwarp();

        // ---- d1 (packed) ----
        {
            u64 acc[NQ];
            float bd1 = smem[OFF_BD1 + lane];
            u64 bd = pack2(bd1, bd1);
            #pragma unroll
            for (int t = 0; t < NQ; t++) acc[t] = bd;
            #pragma unroll
            for (int hq = 0; hq < 8; hq++) {
                u64 w0 = pack2(smem[OFF_WD1 + (4 * hq + 0) * 32 + lane], smem[OFF_WD1 + (4 * hq + 0) * 32 + lane]);
                u64 w1 = pack2(smem[OFF_WD1 + (4 * hq + 1) * 32 + lane], smem[OFF_WD1 + (4 * hq + 1) * 32 + lane]);
                u64 w2 = pack2(smem[OFF_WD1 + (4 * hq + 2) * 32 + lane], smem[OFF_WD1 + (4 * hq + 2) * 32 + lane]);
                u64 w3 = pack2(smem[OFF_WD1 + (4 * hq + 3) * 32 + lane], smem[OFF_WD1 + (4 * hq + 3) * 32 + lane]);
                #pragma unroll
                for (int t = 0; t < NQ; t++) {
                    ulonglong2 qa = *reinterpret_cast<const ulonglong2*>(kpad + t * 64 + 8 * hq);
                    ulonglong2 qb = *reinterpret_cast<const ulonglong2*>(kpad + t * 64 + 8 * hq + 4);
                    acc[t] = ffma2(qa.x, w0, acc[t]);
                    acc[t] = ffma2(qa.y, w1, acc[t]);
                    acc[t] = ffma2(qb.x, w2, acc[t]);
                    acc[t] = ffma2(qb.y, w3, acc[t]);
                }
            }
            __syncwarp();   // p dead; misc becomes d1 output (stride 64)
            #pragma unroll
            for (int t = 0; t < NQ; t++)
                *(u64*)(misc + t * 64 + 2 * lane) = leaky2(acc[t]);
        }
        __syncwarp();

        // ---- d2 + residual (packed), final reduce + sigmoid ----
        {
            u64 acc[NQ];
            float bd2 = smem[OFF_BD2 + lane];
            #pragma unroll
            for (int t = 0; t < NQ; t++)
                acc[t] = pack2(bd2 + r0[t], bd2 + r1[t]);
            #pragma unroll
            for (int hq = 0; hq < 8; hq++) {
                u64 w0 = pack2(smem[OFF_WD2 + (4 * hq + 0) * 32 + lane], smem[OFF_WD2 + (4 * hq + 0) * 32 + lane]);
                u64 w1 = pack2(smem[OFF_WD2 + (4 * hq + 1) * 32 + lane], smem[OFF_WD2 + (4 * hq + 1) * 32 + lane]);
                u64 w2 = pack2(smem[OFF_WD2 + (4 * hq + 2) * 32 + lane], smem[OFF_WD2 + (4 * hq + 2) * 32 + lane]);
                u64 w3 = pack2(smem[OFF_WD2 + (4 * hq + 3) * 32 + lane], smem[OFF_WD2 + (4 * hq + 3) * 32 + lane]);
                #pragma unroll
                for (int t = 0; t < NQ; t++) {
                    ulonglong2 qa = *reinterpret_cast<const ulonglong2*>(misc + t * 64 + 8 * hq);
                    ulonglong2 qb = *reinterpret_cast<const ulonglong2*>(misc + t * 64 + 8 * hq + 4);
                    acc[t] = ffma2(qa.x, w0, acc[t]);
                    acc[t] = ffma2(qa.y, w1, acc[t]);
                    acc[t] = ffma2(qb.x, w2, acc[t]);
                    acc[t] = ffma2(qb.y, w3, acc[t]);
                }
            }

            float wsv = smem[OFF_WS + lane];
            u64 wsv2 = pack2(wsv, wsv);
            u64 outpair = 0ull;
            #pragma unroll
            for (int t = 0; t < NQ; t++) {
                u64 val = fmul2(acc[t], wsv2);
                #pragma unroll
                for (int o = 16; o > 0; o >>= 1)
                    val = fadd2(val, __shfl_xor_sync(FULL, val, o));
                if (lane == t) outpair = val;
            }
            if (lane < NQ) {
                float z0, z1; unpack2(outpair, z0, z1);
                float bs = smem[OFF_BS];
                out[b0 * NQ + lane] = __fdividef(1.f, 1.f + __expf(-(z0 + bs)));
                out[b1 * NQ + lane] = __fdividef(1.f, 1.f + __expf(-(z1 + bs)));
            }
        }
        __syncwarp();   // scratch reused next iteration
    }
}

extern "C" void kernel_launch(void* const* d_in, const int* in_sizes, int n_in,
                              void* d_out, int out_size)
{
    const float* x         = (const float*)d_in[0];
    const void*  mraw      = d_in[1];
    const float* positions = (const float*)d_in[2];
    const float* W_up = (const float*)d_in[3];
    const float* b_up = (const float*)d_in[4];
    const float* W_ud = (const float*)d_in[5];
    const float* b_ud = (const float*)d_in[6];
    const float* W_q  = (const float*)d_in[7];
    const float* b_q  = (const float*)d_in[8];
    const float* W_k  = (const float*)d_in[9];
    const float* b_k  = (const float*)d_in[10];
    const float* W_v  = (const float*)d_in[11];
    const float* b_v  = (const float*)d_in[12];
    const float* W_d1 = (const float*)d_in[13];
    const float* b_d1 = (const float*)d_in[14];
    const float* W_d2 = (const float*)d_in[15];
    const float* b_d2 = (const float*)d_in[16];
    const float* W_s  = (const float*)d_in[17];
    const float* b_s  = (const float*)d_in[18];
    float* out = (float*)d_out;

    const int B = in_sizes[0] / 34;
    const size_t smem_bytes = (size_t)SMEM_FLOATS * sizeof(float);

    detect_mask_kernel<<<1, 32>>>(mraw);

    cudaFuncSetAttribute(score_mechain_kernel,
                         cudaFuncAttributeMaxDynamicSharedMemorySize,
                         (int)smem_bytes);
    score_mechain_kernel<<<148, NT, smem_bytes>>>(
        x, mraw, positions, W_up, b_up, W_ud, b_ud, W_q, b_q, W_k, b_k,
        W_v, b_v, W_d1, b_d1, W_d2, b_d2, W_s, b_s, out, B);
}